// round 1
// baseline (speedup 1.0000x reference)
#include <cuda_runtime.h>
#include <cuda_bf16.h>
#include <math.h>

// Problem constants (fixed for MoELayer_7687991460157)
#define NTOK 4096      // T*B = 1024*4
#define DDIM 1024
#define HDIM 2048
#define ODIM 1024
#define NEXP 8

// ---------------- scratch (device globals; no allocation allowed) ----------
__device__ float g_xn[(size_t)NTOK * DDIM];          // 16 MB  layernorm output
__device__ float g_h[(size_t)2 * NTOK * HDIM];       // 64 MB  layer-1 activations per assignment slot
__device__ float g_y[(size_t)2 * NTOK * ODIM];       // 32 MB  layer-2 outputs per assignment slot
__device__ int   g_cnt[NEXP];                        // per-expert token counts
__device__ int   g_slots[NEXP * NTOK];               // per-expert slot lists (slot = 2n+k)
__device__ float g_prob[2 * NTOK];                   // top-2 softmax probs per token

__device__ __forceinline__ float gelu_exact(float v) {
    return 0.5f * v * (1.0f + erff(v * 0.70710678118654752440f));
}

// ---------------- kernel 0: zero counters (graph-replay safe) --------------
__global__ void zero_kernel() {
    if (threadIdx.x < NEXP) g_cnt[threadIdx.x] = 0;
}

// ---------------- kernel 1: LN + router + top2 + scatter -------------------
__global__ __launch_bounds__(256)
void ln_router_kernel(const float* __restrict__ x,
                      const float* __restrict__ gamma,
                      const float* __restrict__ beta,
                      const float* __restrict__ rw,
                      float* __restrict__ logits_out,
                      int write_logits)
{
    const int n = blockIdx.x;
    const int tid = threadIdx.x;
    __shared__ float sx[DDIM];
    __shared__ float red[256];
    __shared__ float sstat[2];
    __shared__ float lg[NEXP];

    const float* xr = x + (size_t)n * DDIM;
    float s = 0.f;
    for (int i = tid; i < DDIM; i += 256) { float v = xr[i]; sx[i] = v; s += v; }
    red[tid] = s; __syncthreads();
    for (int st = 128; st > 0; st >>= 1) { if (tid < st) red[tid] += red[tid + st]; __syncthreads(); }
    if (tid == 0) sstat[0] = red[0] * (1.0f / DDIM);
    __syncthreads();
    const float mu = sstat[0];
    float s2 = 0.f;
    for (int i = tid; i < DDIM; i += 256) { float v = sx[i] - mu; s2 += v * v; }
    red[tid] = s2; __syncthreads();
    for (int st = 128; st > 0; st >>= 1) { if (tid < st) red[tid] += red[tid + st]; __syncthreads(); }
    if (tid == 0) sstat[1] = rsqrtf(red[0] * (1.0f / DDIM) + 1e-5f);
    __syncthreads();
    const float rstd = sstat[1];
    for (int i = tid; i < DDIM; i += 256) {
        float v = (sx[i] - mu) * rstd * gamma[i] + beta[i];
        sx[i] = v;
        g_xn[(size_t)n * DDIM + i] = v;
    }
    __syncthreads();

    // router: warp w -> expert w (8 warps, 8 experts)
    const int w = tid >> 5, lane = tid & 31;
    {
        const float* r = rw + w * DDIM;
        float p = 0.f;
        for (int i = lane; i < DDIM; i += 32) p += sx[i] * r[i];
        #pragma unroll
        for (int o = 16; o > 0; o >>= 1) p += __shfl_down_sync(0xffffffffu, p, o);
        if (lane == 0) lg[w] = p;
    }
    __syncthreads();

    if (tid == 0) {
        if (write_logits) {
            #pragma unroll
            for (int e = 0; e < NEXP; e++) logits_out[(size_t)n * NEXP + e] = lg[e];
        }
        int i0 = 0;
        #pragma unroll
        for (int e = 1; e < NEXP; e++) if (lg[e] > lg[i0]) i0 = e;
        int i1 = (i0 == 0) ? 1 : 0;
        #pragma unroll
        for (int e = 0; e < NEXP; e++) if (e != i0 && lg[e] > lg[i1]) i1 = e;
        float q = expf(lg[i1] - lg[i0]);
        float inv = 1.0f / (1.0f + q);
        g_prob[2 * n]     = inv;
        g_prob[2 * n + 1] = q * inv;
        int p0 = atomicAdd(&g_cnt[i0], 1); g_slots[i0 * NTOK + p0] = 2 * n;
        int p1 = atomicAdd(&g_cnt[i1], 1); g_slots[i1 * NTOK + p1] = 2 * n + 1;
    }
}

// ---------------- kernels 2/3: grouped SGEMM + bias + GELU -----------------
// LAYER 1: A = g_xn (row = slot>>1, K=1024), B = w1[e] (1024x2048), out = g_h
// LAYER 2: A = g_h  (row = slot,    K=2048), B = w2[e] (2048x1024), out = g_y
template<int LAYER>
__global__ __launch_bounds__(256)
void gemm_gelu_kernel(const float* __restrict__ Wall, const float* __restrict__ ball)
{
    constexpr int BM = 128, BN = 64, BK = 16;
    constexpr int Kdim  = (LAYER == 1) ? DDIM : HDIM;
    constexpr int Ncols = (LAYER == 1) ? HDIM : ODIM;
    constexpr int SHIFT = (LAYER == 1) ? 1 : 0;
    const float* __restrict__ A = (LAYER == 1) ? g_xn : g_h;
    float* __restrict__ Out     = (LAYER == 1) ? g_h  : g_y;

    const int e   = blockIdx.z;
    const int cnt = g_cnt[e];
    const int m0  = blockIdx.x * BM;
    if (m0 >= cnt) return;
    const int n0 = blockIdx.y * BN;
    const float* __restrict__ B    = Wall + (size_t)e * ((size_t)Kdim * Ncols);
    const float* __restrict__ bias = ball + e * Ncols;

    __shared__ float As[BK][BM + 1];   // +1 pad: avoid 16-way STS conflict (stride over kk)
    __shared__ float Bs[BK][BN];
    __shared__ int srow[BM];
    __shared__ int sarow[BM];

    const int tid = threadIdx.x;
    for (int i = tid; i < BM; i += 256) {
        int r = m0 + i;
        int slot = (r < cnt) ? g_slots[e * NTOK + r] : -1;
        srow[i]  = slot;
        sarow[i] = (slot >= 0) ? (slot >> SHIFT) : 0;
    }
    __syncthreads();

    float acc[8][4];
    #pragma unroll
    for (int i = 0; i < 8; i++)
        #pragma unroll
        for (int j = 0; j < 4; j++) acc[i][j] = 0.f;

    const int ty = tid >> 4, tx = tid & 15;

    for (int k0 = 0; k0 < Kdim; k0 += BK) {
        // load A tile (128x16), gathered rows; 8 elems/thread, coalesced 16-wide
        #pragma unroll
        for (int l = 0; l < 8; l++) {
            int idx = tid + l * 256;
            int r = idx >> 4, kk = idx & 15;
            float v = 0.f;
            if (srow[r] >= 0) v = A[(size_t)sarow[r] * Kdim + (k0 + kk)];
            As[kk][r] = v;
        }
        // load B tile (16x64); 4 elems/thread, coalesced 64-wide
        #pragma unroll
        for (int l = 0; l < 4; l++) {
            int idx = tid + l * 256;
            int kk = idx >> 6, c = idx & 63;
            Bs[kk][c] = B[(size_t)(k0 + kk) * Ncols + (n0 + c)];
        }
        __syncthreads();
        #pragma unroll
        for (int kk = 0; kk < BK; kk++) {
            float a[8], b[4];
            #pragma unroll
            for (int i = 0; i < 8; i++) a[i] = As[kk][ty * 8 + i];
            #pragma unroll
            for (int j = 0; j < 4; j++) b[j] = Bs[kk][tx * 4 + j];
            #pragma unroll
            for (int i = 0; i < 8; i++)
                #pragma unroll
                for (int j = 0; j < 4; j++)
                    acc[i][j] = fmaf(a[i], b[j], acc[i][j]);
        }
        __syncthreads();
    }

    #pragma unroll
    for (int i = 0; i < 8; i++) {
        int rt = ty * 8 + i;
        int slot = srow[rt];
        if (slot < 0) continue;
        float* orow = Out + (size_t)slot * Ncols + n0 + tx * 4;
        #pragma unroll
        for (int j = 0; j < 4; j++) {
            float v = acc[i][j] + bias[n0 + tx * 4 + j];
            orow[j] = gelu_exact(v);
        }
    }
}

// ---------------- kernel 4: combine + mask ---------------------------------
__global__ __launch_bounds__(256)
void combine_kernel(const float* __restrict__ mask, float* __restrict__ out)
{
    const int n = blockIdx.x;
    const int tid = threadIdx.x;
    const float m  = mask[n];
    const float p0 = g_prob[2 * n] * m;
    const float p1 = g_prob[2 * n + 1] * m;
    const float* y0 = g_y + (size_t)(2 * n) * ODIM;
    const float* y1 = y0 + ODIM;
    float* o = out + (size_t)n * ODIM;
    for (int c = tid; c < ODIM; c += 256)
        o[c] = p0 * y0[c] + p1 * y1[c];
}

// ---------------- launch ----------------------------------------------------
extern "C" void kernel_launch(void* const* d_in, const int* in_sizes, int n_in,
                              void* d_out, int out_size)
{
    const float* x     = (const float*)d_in[0];
    const float* mask  = (const float*)d_in[1];
    const float* gamma = (const float*)d_in[2];
    const float* beta  = (const float*)d_in[3];
    const float* rw    = (const float*)d_in[4];
    const float* w1    = (const float*)d_in[5];
    const float* b1    = (const float*)d_in[6];
    const float* w2    = (const float*)d_in[7];
    const float* b2    = (const float*)d_in[8];
    float* out = (float*)d_out;

    const int TBO = NTOK * ODIM;                       // 4,194,304
    const int write_logits = (out_size >= TBO + NTOK * NEXP) ? 1 : 0;

    zero_kernel<<<1, 32>>>();
    ln_router_kernel<<<NTOK, 256>>>(x, gamma, beta, rw, out + TBO, write_logits);
    gemm_gelu_kernel<1><<<dim3(NTOK / 128, HDIM / 64, NEXP), 256>>>(w1, b1);
    gemm_gelu_kernel<2><<<dim3(NTOK / 128, ODIM / 64, NEXP), 256>>>(w2, b2);
    combine_kernel<<<NTOK, 256>>>(mask, out);
}

// round 4
// speedup vs baseline: 5.2250x; 5.2250x over previous
#include <cuda_runtime.h>
#include <cuda_bf16.h>
#include <math.h>
#include <cstdint>

#define NTOK 4096      // T*B
#define DDIM 1024
#define HDIM 2048
#define ODIM 1024
#define NEXP 8
#define EMAX 4096      // max tokens per expert

// ---------------- scratch (device globals; no allocation allowed) ----------
__device__ float g_xn[(size_t)NTOK * DDIM];                          // 16 MB
__device__ float g_y[(size_t)2 * NTOK * ODIM];                       // 32 MB
__device__ int   g_cnt[NEXP];
__device__ int   g_slots[NEXP * NTOK];
__device__ float g_prob[2 * NTOK];
__device__ __nv_bfloat16 g_A1[(size_t)NEXP * EMAX * (2 * DDIM)];     // 134 MB [hi K | lo K]
__device__ __nv_bfloat16 g_A2[(size_t)NEXP * EMAX * (2 * HDIM)];     // 268 MB
__device__ __nv_bfloat16 g_B1[(size_t)NEXP * HDIM * (2 * DDIM)];     // 67 MB  [N][hi K | lo K]
__device__ __nv_bfloat16 g_B2[(size_t)NEXP * ODIM * (2 * HDIM)];     // 67 MB

// ---------------- PTX helpers ----------------------------------------------
__device__ __forceinline__ uint32_t smem_to_u32(const void* p) {
    uint32_t a;
    asm("{ .reg .u64 t; cvta.to.shared.u64 t, %1; cvt.u32.u64 %0, t; }" : "=r"(a) : "l"(p));
    return a;
}
#define CP_ASYNC16(saddr, gptr) \
    asm volatile("cp.async.cg.shared.global [%0], [%1], 16;" :: "r"(saddr), "l"(gptr))
#define CP_COMMIT() asm volatile("cp.async.commit_group;" ::: "memory")
#define CP_WAIT1()  asm volatile("cp.async.wait_group 1;" ::: "memory")
#define LDSM_X4(R, addr) \
    asm volatile("ldmatrix.sync.aligned.m8n8.x4.shared.b16 {%0,%1,%2,%3}, [%4];" \
                 : "=r"((R)[0]), "=r"((R)[1]), "=r"((R)[2]), "=r"((R)[3]) : "r"(addr))
#define MMA16816(D, A, B0, B1) \
    asm volatile("mma.sync.aligned.m16n8k16.row.col.f32.bf16.bf16.f32 " \
        "{%0,%1,%2,%3}, {%4,%5,%6,%7}, {%8,%9}, {%0,%1,%2,%3};" \
        : "+f"((D)[0]), "+f"((D)[1]), "+f"((D)[2]), "+f"((D)[3]) \
        : "r"((A)[0]), "r"((A)[1]), "r"((A)[2]), "r"((A)[3]), "r"(B0), "r"(B1))

__device__ __forceinline__ float gelu_exact(float v) {
    return 0.5f * v * (1.0f + erff(v * 0.70710678118654752440f));
}

// ---------------- kernel 0: zero counters ----------------------------------
__global__ void zero_kernel() {
    if (threadIdx.x < NEXP) g_cnt[threadIdx.x] = 0;
}

// ---------------- kernel 1: LN + router + top2 + scatter -------------------
__global__ __launch_bounds__(256)
void ln_router_kernel(const float* __restrict__ x,
                      const float* __restrict__ gamma,
                      const float* __restrict__ beta,
                      const float* __restrict__ rw,
                      float* __restrict__ logits_out,
                      int write_logits)
{
    const int n = blockIdx.x;
    const int tid = threadIdx.x;
    __shared__ float sx[DDIM];
    __shared__ float red[256];
    __shared__ float sstat[2];
    __shared__ float lg[NEXP];

    const float* xr = x + (size_t)n * DDIM;
    float s = 0.f;
    for (int i = tid; i < DDIM; i += 256) { float v = xr[i]; sx[i] = v; s += v; }
    red[tid] = s; __syncthreads();
    for (int st = 128; st > 0; st >>= 1) { if (tid < st) red[tid] += red[tid + st]; __syncthreads(); }
    if (tid == 0) sstat[0] = red[0] * (1.0f / DDIM);
    __syncthreads();
    const float mu = sstat[0];
    float s2 = 0.f;
    for (int i = tid; i < DDIM; i += 256) { float v = sx[i] - mu; s2 += v * v; }
    red[tid] = s2; __syncthreads();
    for (int st = 128; st > 0; st >>= 1) { if (tid < st) red[tid] += red[tid + st]; __syncthreads(); }
    if (tid == 0) sstat[1] = rsqrtf(red[0] * (1.0f / DDIM) + 1e-5f);
    __syncthreads();
    const float rstd = sstat[1];
    for (int i = tid; i < DDIM; i += 256) {
        float v = (sx[i] - mu) * rstd * gamma[i] + beta[i];
        sx[i] = v;
        g_xn[(size_t)n * DDIM + i] = v;
    }
    __syncthreads();

    const int w = tid >> 5, lane = tid & 31;
    {
        const float* r = rw + w * DDIM;
        float p = 0.f;
        for (int i = lane; i < DDIM; i += 32) p += sx[i] * r[i];
        #pragma unroll
        for (int o = 16; o > 0; o >>= 1) p += __shfl_down_sync(0xffffffffu, p, o);
        if (lane == 0) lg[w] = p;
    }
    __syncthreads();

    if (tid == 0) {
        if (write_logits) {
            #pragma unroll
            for (int e = 0; e < NEXP; e++) logits_out[(size_t)n * NEXP + e] = lg[e];
        }
        int i0 = 0;
        #pragma unroll
        for (int e = 1; e < NEXP; e++) if (lg[e] > lg[i0]) i0 = e;
        int i1 = (i0 == 0) ? 1 : 0;
        #pragma unroll
        for (int e = 0; e < NEXP; e++) if (e != i0 && lg[e] > lg[i1]) i1 = e;
        float q = expf(lg[i1] - lg[i0]);
        float inv = 1.0f / (1.0f + q);
        g_prob[2 * n]     = inv;
        g_prob[2 * n + 1] = q * inv;
        int p0 = atomicAdd(&g_cnt[i0], 1); g_slots[i0 * NTOK + p0] = 2 * n;
        int p1 = atomicAdd(&g_cnt[i1], 1); g_slots[i1 * NTOK + p1] = 2 * n + 1;
    }
}

// ---------------- kernel 2: pack tokens into per-expert A1 (hi|lo bf16) ----
__global__ __launch_bounds__(256)
void pack1_kernel()
{
    const int e = blockIdx.y;
    const int m0 = blockIdx.x * 128;
    const int cnt = g_cnt[e];
    if (m0 >= cnt) return;
    const int tid = threadIdx.x;
    __nv_bfloat16* outp = g_A1 + ((size_t)e * EMAX) * (2 * DDIM);
    for (int idx = tid; idx < 128 * 256; idx += 256) {
        int r = idx >> 8;
        int c4 = idx & 255;
        int row = m0 + r;
        if (row >= cnt) continue;
        int token = g_slots[e * NTOK + row] >> 1;
        float4 v = ((const float4*)g_xn)[(size_t)token * 256 + c4];
        size_t rb = (size_t)row * (2 * DDIM);
        int c = c4 * 4;
        float vv[4] = {v.x, v.y, v.z, v.w};
        uint32_t hp[2], lp[2];
        #pragma unroll
        for (int q = 0; q < 2; q++) {
            __nv_bfloat16 h0 = __float2bfloat16(vv[2*q]);
            __nv_bfloat16 l0 = __float2bfloat16(vv[2*q] - __bfloat162float(h0));
            __nv_bfloat16 h1 = __float2bfloat16(vv[2*q+1]);
            __nv_bfloat16 l1 = __float2bfloat16(vv[2*q+1] - __bfloat162float(h1));
            hp[q] = (uint32_t)*(uint16_t*)&h0 | ((uint32_t)*(uint16_t*)&h1 << 16);
            lp[q] = (uint32_t)*(uint16_t*)&l0 | ((uint32_t)*(uint16_t*)&l1 << 16);
        }
        *(uint2*)&outp[rb + c] = make_uint2(hp[0], hp[1]);
        *(uint2*)&outp[rb + DDIM + c] = make_uint2(lp[0], lp[1]);
    }
}

// ---------------- kernel 3: weight transpose + hi/lo split -----------------
template<int LAYER>
__global__ __launch_bounds__(256)
void wcvt_kernel(const float* __restrict__ W)
{
    constexpr int Kd = (LAYER == 1) ? DDIM : HDIM;
    constexpr int Nd = (LAYER == 1) ? HDIM : ODIM;
    __nv_bfloat16* Bout = (LAYER == 1) ? g_B1 : g_B2;
    const int e = blockIdx.z;
    const int d0 = blockIdx.x * 32;
    const int h0 = blockIdx.y * 32;
    __shared__ float st[32][33];
    const int tx = threadIdx.x & 31, ty = threadIdx.x >> 5;
    #pragma unroll
    for (int i = 0; i < 4; i++) {
        int dl = ty + 8 * i;
        st[dl][tx] = W[((size_t)e * Kd + d0 + dl) * Nd + h0 + tx];
    }
    __syncthreads();
    #pragma unroll
    for (int i = 0; i < 4; i++) {
        int hl = ty + 8 * i;
        float v = st[tx][hl];
        __nv_bfloat16 hi = __float2bfloat16(v);
        __nv_bfloat16 lo = __float2bfloat16(v - __bfloat162float(hi));
        size_t rb = ((size_t)e * Nd + h0 + hl) * (size_t)(2 * Kd);
        Bout[rb + d0 + tx] = hi;
        Bout[rb + Kd + d0 + tx] = lo;
    }
}

// ---------------- kernels 4/5: grouped bf16x3 GEMM via mma.sync ------------
// Tile 128x128, BK=64 (one 128B SW128 row / tile row), 2-stage cp.async.
// 3 K-segments accumulate: Ahi*Bhi + Alo*Bhi + Ahi*Blo.
template<int LAYER>
__global__ __launch_bounds__(256, 2)
void mma_gemm(const float* __restrict__ bias_all)
{
    constexpr int Kd = (LAYER == 1) ? DDIM : HDIM;
    constexpr int Nd = (LAYER == 1) ? HDIM : ODIM;
    constexpr int CPS = Kd / 64;
    constexpr int NCH = 3 * CPS;
    constexpr int STAGE_BYTES = 32768;   // A 16K + B 16K
    const __nv_bfloat16* __restrict__ Aall = (LAYER == 1) ? g_A1 : g_A2;
    const __nv_bfloat16* __restrict__ Ball = (LAYER == 1) ? g_B1 : g_B2;

    const int e = blockIdx.z;
    const int cnt = g_cnt[e];
    const int m0 = blockIdx.x * 128;
    if (m0 >= cnt) return;
    const int n0 = blockIdx.y * 128;

    extern __shared__ __align__(1024) char smem[];
    const uint32_t smem_u = smem_to_u32(smem);

    const int tid = threadIdx.x;
    const int lane = tid & 31;
    const int wid = tid >> 5;
    const int wm = wid >> 1;          // 0..3 -> 32-row block
    const int wn = wid & 1;           // 0..1 -> 64-col block

    const size_t rstride = 2 * Kd;
    const __nv_bfloat16* Abase = Aall + ((size_t)e * EMAX + m0) * rstride;
    const __nv_bfloat16* Bbase = Ball + ((size_t)e * Nd + n0) * rstride;

    // per-thread load indices: 128 rows x 8 x 16B per tile; 4 chunks/thread
    const int lr = tid >> 3;          // base row (stride 32 over l)
    const int lch = tid & 7;          // 16B chunk in row
    const uint32_t lsw = (uint32_t)(lch * 16) ^ (uint32_t)((lr & 7) << 4);

    float acc[2][8][4];
    #pragma unroll
    for (int i = 0; i < 2; i++)
        #pragma unroll
        for (int j = 0; j < 8; j++)
            #pragma unroll
            for (int q = 0; q < 4; q++) acc[i][j][q] = 0.f;

    auto load_stage = [&](int c, int st) {
        const int seg = c / CPS;
        const int kk = (c - seg * CPS) * 64;
        const int acol = ((seg == 1) ? Kd : 0) + kk;
        const int bcol = ((seg == 2) ? Kd : 0) + kk;
        const uint32_t sA = smem_u + st * STAGE_BYTES;
        const uint32_t sB = sA + 16384;
        #pragma unroll
        for (int l = 0; l < 4; l++) {
            int r = lr + l * 32;
            CP_ASYNC16(sA + (uint32_t)(r * 128) + lsw,
                       (const char*)(Abase + (size_t)r * rstride + acol) + lch * 16);
        }
        #pragma unroll
        for (int l = 0; l < 4; l++) {
            int r = lr + l * 32;
            CP_ASYNC16(sB + (uint32_t)(r * 128) + lsw,
                       (const char*)(Bbase + (size_t)r * rstride + bcol) + lch * 16);
        }
        CP_COMMIT();
    };

    // ldmatrix per-thread row/col components
    const int rowA0 = wm * 32 + (lane & 15);        // + mf*16
    const int kbA = (lane >> 4) * 8;                // k byte base = kbA*2
    const int g = lane >> 3;
    const int rowB0 = wn * 64 + ((g >> 1) << 3) + (lane & 7);   // + ng*16
    const int kbB = (g & 1) * 8;

    auto compute_stage = [&](int st) {
        const uint32_t sA = smem_u + st * STAGE_BYTES;
        const uint32_t sB = sA + 16384;
        #pragma unroll
        for (int ks = 0; ks < 4; ks++) {
            uint32_t af[2][4];
            #pragma unroll
            for (int mf = 0; mf < 2; mf++) {
                int row = rowA0 + mf * 16;
                uint32_t koff = (uint32_t)((ks * 16 + kbA) * 2) ^ (uint32_t)((row & 7) << 4);
                LDSM_X4(af[mf], sA + (uint32_t)(row * 128) + koff);
            }
            #pragma unroll
            for (int ng = 0; ng < 4; ng++) {
                uint32_t bf[4];
                int row = rowB0 + ng * 16;
                uint32_t koff = (uint32_t)((ks * 16 + kbB) * 2) ^ (uint32_t)((row & 7) << 4);
                LDSM_X4(bf, sB + (uint32_t)(row * 128) + koff);
                #pragma unroll
                for (int mf = 0; mf < 2; mf++) {
                    MMA16816(acc[mf][2 * ng],     af[mf], bf[0], bf[1]);
                    MMA16816(acc[mf][2 * ng + 1], af[mf], bf[2], bf[3]);
                }
            }
        }
    };

    load_stage(0, 0);
    load_stage(1, 1);
    for (int c = 0; c < NCH; c++) {
        const int st = c & 1;
        CP_WAIT1();
        __syncthreads();
        compute_stage(st);
        __syncthreads();
        if (c + 2 < NCH) load_stage(c + 2, st);
        else CP_COMMIT();
    }

    // ---------------- epilogue --------------------------------------------
    const float* bias = bias_all + (size_t)e * Nd;
    const int rbase = m0 + wm * 32 + (lane >> 2);
    const int cbase = n0 + wn * 64 + (lane & 3) * 2;

    #pragma unroll
    for (int mf = 0; mf < 2; mf++) {
        #pragma unroll
        for (int cp = 0; cp < 2; cp++) {
            int row = rbase + mf * 16 + cp * 8;
            if (row >= cnt) continue;
            if (LAYER == 1) {
                __nv_bfloat16* orow = g_A2 + ((size_t)e * EMAX + row) * (2 * HDIM);
                #pragma unroll
                for (int nf = 0; nf < 8; nf++) {
                    int col = cbase + nf * 8;
                    float v0 = gelu_exact(acc[mf][nf][2 * cp]     + bias[col]);
                    float v1 = gelu_exact(acc[mf][nf][2 * cp + 1] + bias[col + 1]);
                    __nv_bfloat16 h0 = __float2bfloat16(v0);
                    __nv_bfloat16 l0 = __float2bfloat16(v0 - __bfloat162float(h0));
                    __nv_bfloat16 h1 = __float2bfloat16(v1);
                    __nv_bfloat16 l1 = __float2bfloat16(v1 - __bfloat162float(h1));
                    uint32_t hp = (uint32_t)*(uint16_t*)&h0 | ((uint32_t)*(uint16_t*)&h1 << 16);
                    uint32_t lp = (uint32_t)*(uint16_t*)&l0 | ((uint32_t)*(uint16_t*)&l1 << 16);
                    *(uint32_t*)&orow[col] = hp;
                    *(uint32_t*)&orow[HDIM + col] = lp;
                }
            } else {
                int slot = g_slots[e * NTOK + row];
                float* orow = g_y + (size_t)slot * ODIM;
                #pragma unroll
                for (int nf = 0; nf < 8; nf++) {
                    int col = cbase + nf * 8;
                    float v0 = gelu_exact(acc[mf][nf][2 * cp]     + bias[col]);
                    float v1 = gelu_exact(acc[mf][nf][2 * cp + 1] + bias[col + 1]);
                    *(float2*)&orow[col] = make_float2(v0, v1);
                }
            }
        }
    }
}

// ---------------- kernel 6: combine + mask ---------------------------------
__global__ __launch_bounds__(256)
void combine_kernel(const float* __restrict__ mask, float* __restrict__ out)
{
    const int n = blockIdx.x;
    const int tid = threadIdx.x;
    const float m  = mask[n];
    const float p0 = g_prob[2 * n] * m;
    const float p1 = g_prob[2 * n + 1] * m;
    const float* y0 = g_y + (size_t)(2 * n) * ODIM;
    const float* y1 = y0 + ODIM;
    float* o = out + (size_t)n * ODIM;
    for (int c = tid; c < ODIM; c += 256)
        o[c] = p0 * y0[c] + p1 * y1[c];
}

// ---------------- launch ----------------------------------------------------
extern "C" void kernel_launch(void* const* d_in, const int* in_sizes, int n_in,
                              void* d_out, int out_size)
{
    const float* x     = (const float*)d_in[0];
    const float* mask  = (const float*)d_in[1];
    const float* gamma = (const float*)d_in[2];
    const float* beta  = (const float*)d_in[3];
    const float* rw    = (const float*)d_in[4];
    const float* w1    = (const float*)d_in[5];
    const float* b1    = (const float*)d_in[6];
    const float* w2    = (const float*)d_in[7];
    const float* b2    = (const float*)d_in[8];
    float* out = (float*)d_out;

    const int TBO = NTOK * ODIM;
    const int write_logits = (out_size >= TBO + NTOK * NEXP) ? 1 : 0;
    const int DSMEM = 65536;   // 2 stages x (16K A + 16K B)

    static int attr_done = 0;
    if (!attr_done) {
        cudaFuncSetAttribute(mma_gemm<1>, cudaFuncAttributeMaxDynamicSharedMemorySize, DSMEM);
        cudaFuncSetAttribute(mma_gemm<2>, cudaFuncAttributeMaxDynamicSharedMemorySize, DSMEM);
        attr_done = 1;
    }

    zero_kernel<<<1, 32>>>();
    ln_router_kernel<<<NTOK, 256>>>(x, gamma, beta, rw, out + TBO, write_logits);
    pack1_kernel<<<dim3(EMAX / 128, NEXP), 256>>>();
    wcvt_kernel<1><<<dim3(DDIM / 32, HDIM / 32, NEXP), 256>>>(w1);
    wcvt_kernel<2><<<dim3(HDIM / 32, ODIM / 32, NEXP), 256>>>(w2);
    mma_gemm<1><<<dim3(EMAX / 128, HDIM / 128, NEXP), 256, DSMEM>>>(b1);
    mma_gemm<2><<<dim3(EMAX / 128, ODIM / 128, NEXP), 256, DSMEM>>>(b2);
    combine_kernel<<<NTOK, 256>>>(mask, out);
}

// round 5
// speedup vs baseline: 5.4137x; 1.0361x over previous
#include <cuda_runtime.h>
#include <cuda_bf16.h>
#include <math.h>
#include <cstdint>

#define NTOK 4096      // T*B
#define DDIM 1024
#define HDIM 2048
#define ODIM 1024
#define NEXP 8
#define EMAX 4096      // max tokens per expert

// Panel layout (A and B): per row, K is grouped in 32-element chunks, each
// chunk stored as 64 consecutive bf16 = [hi 0..31 | lo 0..31] (128 bytes).
// Row stride = 2*Kd elements.

// ---------------- scratch (device globals; no allocation allowed) ----------
__device__ float g_xn[(size_t)NTOK * DDIM];                          // 16 MB
__device__ float g_y[(size_t)2 * NTOK * ODIM];                       // 32 MB
__device__ int   g_cnt[NEXP];
__device__ int   g_slots[NEXP * NTOK];
__device__ float g_prob[2 * NTOK];
__device__ __nv_bfloat16 g_A1[(size_t)NEXP * EMAX * (2 * DDIM)];     // 134 MB
__device__ __nv_bfloat16 g_A2[(size_t)NEXP * EMAX * (2 * HDIM)];     // 268 MB
__device__ __nv_bfloat16 g_B1[(size_t)NEXP * HDIM * (2 * DDIM)];     // 67 MB
__device__ __nv_bfloat16 g_B2[(size_t)NEXP * ODIM * (2 * HDIM)];     // 67 MB

// ---------------- PTX helpers ----------------------------------------------
__device__ __forceinline__ uint32_t smem_to_u32(const void* p) {
    uint32_t a;
    asm("{ .reg .u64 t; cvta.to.shared.u64 t, %1; cvt.u32.u64 %0, t; }" : "=r"(a) : "l"(p));
    return a;
}
#define CP_ASYNC16(saddr, gptr) \
    asm volatile("cp.async.cg.shared.global [%0], [%1], 16;" :: "r"(saddr), "l"(gptr))
#define CP_COMMIT() asm volatile("cp.async.commit_group;" ::: "memory")
#define CP_WAIT1()  asm volatile("cp.async.wait_group 1;" ::: "memory")
#define LDSM_X4(R, addr) \
    asm volatile("ldmatrix.sync.aligned.m8n8.x4.shared.b16 {%0,%1,%2,%3}, [%4];" \
                 : "=r"((R)[0]), "=r"((R)[1]), "=r"((R)[2]), "=r"((R)[3]) : "r"(addr))
#define MMA16816(D, A, B0, B1) \
    asm volatile("mma.sync.aligned.m16n8k16.row.col.f32.bf16.bf16.f32 " \
        "{%0,%1,%2,%3}, {%4,%5,%6,%7}, {%8,%9}, {%0,%1,%2,%3};" \
        : "+f"((D)[0]), "+f"((D)[1]), "+f"((D)[2]), "+f"((D)[3]) \
        : "r"((A)[0]), "r"((A)[1]), "r"((A)[2]), "r"((A)[3]), "r"(B0), "r"(B1))

__device__ __forceinline__ float gelu_exact(float v) {
    return 0.5f * v * (1.0f + erff(v * 0.70710678118654752440f));
}
__device__ __forceinline__ uint32_t pack_hi2(float a, float b) {
    __nv_bfloat16 ha = __float2bfloat16(a), hb = __float2bfloat16(b);
    return (uint32_t)*(uint16_t*)&ha | ((uint32_t)*(uint16_t*)&hb << 16);
}
__device__ __forceinline__ uint32_t pack_lo2(float a, float b) {
    __nv_bfloat16 ha = __float2bfloat16(a), hb = __float2bfloat16(b);
    __nv_bfloat16 la = __float2bfloat16(a - __bfloat162float(ha));
    __nv_bfloat16 lb = __float2bfloat16(b - __bfloat162float(hb));
    return (uint32_t)*(uint16_t*)&la | ((uint32_t)*(uint16_t*)&lb << 16);
}

// ---------------- kernel 0: zero counters ----------------------------------
__global__ void zero_kernel() {
    if (threadIdx.x < NEXP) g_cnt[threadIdx.x] = 0;
}

// ---------------- kernel 1: LN + router + top2 + scatter -------------------
__global__ __launch_bounds__(256)
void ln_router_kernel(const float* __restrict__ x,
                      const float* __restrict__ gamma,
                      const float* __restrict__ beta,
                      const float* __restrict__ rw,
                      float* __restrict__ logits_out,
                      int write_logits)
{
    const int n = blockIdx.x;
    const int tid = threadIdx.x;
    __shared__ float sx[DDIM];
    __shared__ float red[256];
    __shared__ float sstat[2];
    __shared__ float lg[NEXP];

    const float* xr = x + (size_t)n * DDIM;
    float s = 0.f;
    for (int i = tid; i < DDIM; i += 256) { float v = xr[i]; sx[i] = v; s += v; }
    red[tid] = s; __syncthreads();
    for (int st = 128; st > 0; st >>= 1) { if (tid < st) red[tid] += red[tid + st]; __syncthreads(); }
    if (tid == 0) sstat[0] = red[0] * (1.0f / DDIM);
    __syncthreads();
    const float mu = sstat[0];
    float s2 = 0.f;
    for (int i = tid; i < DDIM; i += 256) { float v = sx[i] - mu; s2 += v * v; }
    red[tid] = s2; __syncthreads();
    for (int st = 128; st > 0; st >>= 1) { if (tid < st) red[tid] += red[tid + st]; __syncthreads(); }
    if (tid == 0) sstat[1] = rsqrtf(red[0] * (1.0f / DDIM) + 1e-5f);
    __syncthreads();
    const float rstd = sstat[1];
    for (int i = tid; i < DDIM; i += 256) {
        float v = (sx[i] - mu) * rstd * gamma[i] + beta[i];
        sx[i] = v;
        g_xn[(size_t)n * DDIM + i] = v;
    }
    __syncthreads();

    const int w = tid >> 5, lane = tid & 31;
    {
        const float* r = rw + w * DDIM;
        float p = 0.f;
        for (int i = lane; i < DDIM; i += 32) p += sx[i] * r[i];
        #pragma unroll
        for (int o = 16; o > 0; o >>= 1) p += __shfl_down_sync(0xffffffffu, p, o);
        if (lane == 0) lg[w] = p;
    }
    __syncthreads();

    if (tid == 0) {
        if (write_logits) {
            #pragma unroll
            for (int e = 0; e < NEXP; e++) logits_out[(size_t)n * NEXP + e] = lg[e];
        }
        int i0 = 0;
        #pragma unroll
        for (int e = 1; e < NEXP; e++) if (lg[e] > lg[i0]) i0 = e;
        int i1 = (i0 == 0) ? 1 : 0;
        #pragma unroll
        for (int e = 0; e < NEXP; e++) if (e != i0 && lg[e] > lg[i1]) i1 = e;
        float q = expf(lg[i1] - lg[i0]);
        float inv = 1.0f / (1.0f + q);
        g_prob[2 * n]     = inv;
        g_prob[2 * n + 1] = q * inv;
        int p0 = atomicAdd(&g_cnt[i0], 1); g_slots[i0 * NTOK + p0] = 2 * n;
        int p1 = atomicAdd(&g_cnt[i1], 1); g_slots[i1 * NTOK + p1] = 2 * n + 1;
    }
}

// ---------------- kernel 2: pack tokens into per-expert A1 -----------------
__global__ __launch_bounds__(256)
void pack1_kernel()
{
    const int e = blockIdx.y;
    const int m0 = blockIdx.x * 128;
    const int cnt = g_cnt[e];
    if (m0 >= cnt) return;
    const int tid = threadIdx.x;
    __nv_bfloat16* outp = g_A1 + ((size_t)e * EMAX) * (2 * DDIM);
    for (int idx = tid; idx < 128 * 256; idx += 256) {
        int r = idx >> 8;
        int c4 = idx & 255;
        int row = m0 + r;
        if (row >= cnt) continue;
        int token = g_slots[e * NTOK + row] >> 1;
        float4 v = ((const float4*)g_xn)[(size_t)token * 256 + c4];
        size_t rb = (size_t)row * (2 * DDIM);
        int c = c4 * 4;               // k index, multiple of 4
        int ch = c >> 5, pos = c & 31;
        uint2 hp = make_uint2(pack_hi2(v.x, v.y), pack_hi2(v.z, v.w));
        uint2 lp = make_uint2(pack_lo2(v.x, v.y), pack_lo2(v.z, v.w));
        *(uint2*)&outp[rb + ch * 64 + pos]      = hp;
        *(uint2*)&outp[rb + ch * 64 + pos + 32] = lp;
    }
}

// ---------------- kernel 3: weight transpose + hi/lo split -----------------
// W [E][Kd][Nd] (fp32) -> B [E][Nd][chunked hi|lo] (bf16)
template<int LAYER>
__global__ __launch_bounds__(256)
void wcvt_kernel(const float* __restrict__ W)
{
    constexpr int Kd = (LAYER == 1) ? DDIM : HDIM;
    constexpr int Nd = (LAYER == 1) ? HDIM : ODIM;
    __nv_bfloat16* Bout = (LAYER == 1) ? g_B1 : g_B2;
    const int e = blockIdx.z;
    const int d0 = blockIdx.x * 32;   // K chunk base (one 32-chunk per block)
    const int h0 = blockIdx.y * 32;   // N base
    __shared__ float st[32][33];
    const int tid = threadIdx.x;
    {
        int dl = tid >> 3, q = tid & 7;
        float4 v = *(const float4*)(W + ((size_t)e * Kd + d0 + dl) * Nd + h0 + q * 4);
        st[dl][q * 4 + 0] = v.x; st[dl][q * 4 + 1] = v.y;
        st[dl][q * 4 + 2] = v.z; st[dl][q * 4 + 3] = v.w;
    }
    __syncthreads();
    const int n = tid >> 3, seg = tid & 7;
    const int isLo = seg >> 2, j0 = (seg & 3) * 8;
    uint32_t pk[4];
    #pragma unroll
    for (int q = 0; q < 4; q++) {
        float a = st[j0 + 2 * q][n], b = st[j0 + 2 * q + 1][n];
        pk[q] = isLo ? pack_lo2(a, b) : pack_hi2(a, b);
    }
    size_t rb = ((size_t)e * Nd + h0 + n) * (size_t)(2 * Kd);
    int off = (d0 >> 5) * 64 + isLo * 32 + j0;
    *(uint4*)&Bout[rb + off] = *(uint4*)pk;
}

// ---------------- kernels 4/5: grouped bf16x3 GEMM via mma.sync ------------
// Tile 128x128; chunk = 32 K (hi+lo in one 128B row). 3-stage cp.async.
// Per chunk, accumulate Ahi*Bhi + Alo*Bhi + Ahi*Blo from the SAME smem tiles.
template<int LAYER>
__global__ __launch_bounds__(256, 2)
void mma_gemm(const float* __restrict__ bias_all)
{
    constexpr int Kd = (LAYER == 1) ? DDIM : HDIM;
    constexpr int Nd = (LAYER == 1) ? HDIM : ODIM;
    constexpr int NCH = Kd / 32;
    constexpr int STAGE_BYTES = 32768;   // A 16K + B 16K
    const __nv_bfloat16* __restrict__ Aall = (LAYER == 1) ? g_A1 : g_A2;
    const __nv_bfloat16* __restrict__ Ball = (LAYER == 1) ? g_B1 : g_B2;

    const int e = blockIdx.z;
    const int cnt = g_cnt[e];
    const int m0 = blockIdx.x * 128;
    if (m0 >= cnt) return;
    const int n0 = blockIdx.y * 128;

    extern __shared__ __align__(1024) char smem[];
    const uint32_t smem_u = smem_to_u32(smem);

    const int tid = threadIdx.x;
    const int lane = tid & 31;
    const int wid = tid >> 5;
    const int wm = wid >> 1;
    const int wn = wid & 1;

    const size_t rstride = 2 * Kd;
    const __nv_bfloat16* Abase = Aall + ((size_t)e * EMAX + m0) * rstride;
    const __nv_bfloat16* Bbase = Ball + ((size_t)e * Nd + n0) * rstride;

    const int lr = tid >> 3;          // base row (4 rows/thread, stride 32)
    const int lch = tid & 7;          // 16B chunk in 128B row
    const uint32_t lsw = (uint32_t)(lch * 16) ^ (uint32_t)((lr & 7) << 4);

    float acc[2][8][4];
    #pragma unroll
    for (int i = 0; i < 2; i++)
        #pragma unroll
        for (int j = 0; j < 8; j++)
            #pragma unroll
            for (int q = 0; q < 4; q++) acc[i][j][q] = 0.f;

    auto load_stage = [&](int c, int st) {
        const int col = c * 64;       // element offset of chunk (hi|lo 128B)
        const uint32_t sA = smem_u + st * STAGE_BYTES;
        const uint32_t sB = sA + 16384;
        #pragma unroll
        for (int l = 0; l < 4; l++) {
            int r = lr + l * 32;
            CP_ASYNC16(sA + (uint32_t)(r * 128) + lsw,
                       (const char*)(Abase + (size_t)r * rstride + col) + lch * 16);
        }
        #pragma unroll
        for (int l = 0; l < 4; l++) {
            int r = lr + l * 32;
            CP_ASYNC16(sB + (uint32_t)(r * 128) + lsw,
                       (const char*)(Bbase + (size_t)r * rstride + col) + lch * 16);
        }
    };

    const int rowA0 = wm * 32 + (lane & 15);
    const int kbA = (lane >> 4) * 8;
    const int g = lane >> 3;
    const int rowB0 = wn * 64 + ((g >> 1) << 3) + (lane & 7);
    const int kbB = (g & 1) * 8;

    auto compute_stage = [&](int st) {
        const uint32_t sA = smem_u + st * STAGE_BYTES;
        const uint32_t sB = sA + 16384;
        #pragma unroll
        for (int ks = 0; ks < 2; ks++) {
            uint32_t ah[2][4], al[2][4];
            #pragma unroll
            for (int mf = 0; mf < 2; mf++) {
                int row = rowA0 + mf * 16;
                uint32_t base = sA + (uint32_t)(row * 128);
                uint32_t sw = (uint32_t)((row & 7) << 4);
                uint32_t kh = (uint32_t)((ks * 16 + kbA) * 2);
                LDSM_X4(ah[mf], base + (kh ^ sw));
                LDSM_X4(al[mf], base + ((kh + 64) ^ sw));
            }
            #pragma unroll
            for (int ng = 0; ng < 4; ng++) {
                int row = rowB0 + ng * 16;
                uint32_t base = sB + (uint32_t)(row * 128);
                uint32_t sw = (uint32_t)((row & 7) << 4);
                uint32_t kh = (uint32_t)((ks * 16 + kbB) * 2);
                uint32_t bh[4], bl[4];
                LDSM_X4(bh, base + (kh ^ sw));
                LDSM_X4(bl, base + ((kh + 64) ^ sw));
                #pragma unroll
                for (int mf = 0; mf < 2; mf++) {
                    MMA16816(acc[mf][2 * ng],     ah[mf], bh[0], bh[1]);
                    MMA16816(acc[mf][2 * ng + 1], ah[mf], bh[2], bh[3]);
                    MMA16816(acc[mf][2 * ng],     al[mf], bh[0], bh[1]);
                    MMA16816(acc[mf][2 * ng + 1], al[mf], bh[2], bh[3]);
                    MMA16816(acc[mf][2 * ng],     ah[mf], bl[0], bl[1]);
                    MMA16816(acc[mf][2 * ng + 1], ah[mf], bl[2], bl[3]);
                }
            }
        }
    };

    load_stage(0, 0); CP_COMMIT();
    load_stage(1, 1); CP_COMMIT();
    for (int c = 0; c < NCH; c++) {
        CP_WAIT1();
        __syncthreads();
        if (c + 2 < NCH) load_stage(c + 2, (c + 2) % 3);
        CP_COMMIT();
        compute_stage(c % 3);
    }

    // ---------------- epilogue --------------------------------------------
    const float* bias = bias_all + (size_t)e * Nd;
    const int rbase = m0 + wm * 32 + (lane >> 2);
    const int cbase = n0 + wn * 64 + (lane & 3) * 2;

    #pragma unroll
    for (int mf = 0; mf < 2; mf++) {
        #pragma unroll
        for (int cp = 0; cp < 2; cp++) {
            int row = rbase + mf * 16 + cp * 8;
            if (row >= cnt) continue;
            if (LAYER == 1) {
                __nv_bfloat16* orow = g_A2 + ((size_t)e * EMAX + row) * (2 * HDIM);
                #pragma unroll
                for (int nf = 0; nf < 8; nf++) {
                    int col = cbase + nf * 8;
                    float v0 = gelu_exact(acc[mf][nf][2 * cp]     + bias[col]);
                    float v1 = gelu_exact(acc[mf][nf][2 * cp + 1] + bias[col + 1]);
                    int ch = col >> 5, pos = col & 31;
                    *(uint32_t*)&orow[ch * 64 + pos]      = pack_hi2(v0, v1);
                    *(uint32_t*)&orow[ch * 64 + pos + 32] = pack_lo2(v0, v1);
                }
            } else {
                int slot = g_slots[e * NTOK + row];
                float* orow = g_y + (size_t)slot * ODIM;
                #pragma unroll
                for (int nf = 0; nf < 8; nf++) {
                    int col = cbase + nf * 8;
                    float v0 = gelu_exact(acc[mf][nf][2 * cp]     + bias[col]);
                    float v1 = gelu_exact(acc[mf][nf][2 * cp + 1] + bias[col + 1]);
                    *(float2*)&orow[col] = make_float2(v0, v1);
                }
            }
        }
    }
}

// ---------------- kernel 6: combine + mask ---------------------------------
__global__ __launch_bounds__(256)
void combine_kernel(const float* __restrict__ mask, float* __restrict__ out)
{
    const int n = blockIdx.x;
    const int tid = threadIdx.x;
    const float m  = mask[n];
    const float p0 = g_prob[2 * n] * m;
    const float p1 = g_prob[2 * n + 1] * m;
    const float* y0 = g_y + (size_t)(2 * n) * ODIM;
    const float* y1 = y0 + ODIM;
    float* o = out + (size_t)n * ODIM;
    for (int c = tid; c < ODIM; c += 256)
        o[c] = p0 * y0[c] + p1 * y1[c];
}

// ---------------- launch ----------------------------------------------------
extern "C" void kernel_launch(void* const* d_in, const int* in_sizes, int n_in,
                              void* d_out, int out_size)
{
    const float* x     = (const float*)d_in[0];
    const float* mask  = (const float*)d_in[1];
    const float* gamma = (const float*)d_in[2];
    const float* beta  = (const float*)d_in[3];
    const float* rw    = (const float*)d_in[4];
    const float* w1    = (const float*)d_in[5];
    const float* b1    = (const float*)d_in[6];
    const float* w2    = (const float*)d_in[7];
    const float* b2    = (const float*)d_in[8];
    float* out = (float*)d_out;

    const int TBO = NTOK * ODIM;
    const int write_logits = (out_size >= TBO + NTOK * NEXP) ? 1 : 0;
    const int DSMEM = 98304;   // 3 stages x (16K A + 16K B)

    static int attr_done = 0;
    if (!attr_done) {
        cudaFuncSetAttribute(mma_gemm<1>, cudaFuncAttributeMaxDynamicSharedMemorySize, DSMEM);
        cudaFuncSetAttribute(mma_gemm<2>, cudaFuncAttributeMaxDynamicSharedMemorySize, DSMEM);
        attr_done = 1;
    }

    zero_kernel<<<1, 32>>>();
    ln_router_kernel<<<NTOK, 256>>>(x, gamma, beta, rw, out + TBO, write_logits);
    pack1_kernel<<<dim3(EMAX / 128, NEXP), 256>>>();
    wcvt_kernel<1><<<dim3(DDIM / 32, HDIM / 32, NEXP), 256>>>(w1);
    wcvt_kernel<2><<<dim3(HDIM / 32, ODIM / 32, NEXP), 256>>>(w2);
    mma_gemm<1><<<dim3(EMAX / 128, HDIM / 128, NEXP), 256, DSMEM>>>(b1);
    mma_gemm<2><<<dim3(EMAX / 128, ODIM / 128, NEXP), 256, DSMEM>>>(b2);
    combine_kernel<<<NTOK, 256>>>(mask, out);
}